// round 14
// baseline (speedup 1.0000x reference)
#include <cuda_runtime.h>
#include <math.h>

#define BB 8
#define NN 4096
#define DIM 1024
#define GRID 296            // 148 SMs x 2 CTAs, all resident
#define TOTAL_ROWS (BB * NN)
#define CHUNK 32            // rows per dynamic grab (divides NN)
#define PF_ROWS 8064        // x rows L2-prefetched during prepass (31.5 MB)
// Every replay consumes exactly TOTAL_ROWS/CHUNK good grabs + GRID failing
// grabs (each block exits on its first failure) -> deterministic per epoch.
#define EPOCH_TICKETS ((unsigned long long)(TOTAL_ROWS + GRID * CHUNK))

// Scratch (no allocation allowed). Zero-initialized at module load.
__device__ float g_q0[BB * DIM];            // direct-write, no zeroing needed
__device__ float g_v2[2][BB * DIM];         // parity-buffered per replay epoch
__device__ float g_scores[BB * NN];
__device__ unsigned int g_b1, g_b2;         // monotonic barrier counters
__device__ unsigned long long g_row;        // monotonic row ticket
__device__ unsigned int g_done[BB];         // monotonic per-batch row counts

__device__ __forceinline__ float warp_sum(float v) {
#pragma unroll
    for (int off = 16; off > 0; off >>= 1)
        v += __shfl_down_sync(0xFFFFFFFFu, v, off);
    return v;
}

// Monotonic grid barrier (atomic arrival, volatile-load poll).
__device__ __forceinline__ void grid_barrier(unsigned int* ctr) {
    __shared__ unsigned int s_tk;
    __threadfence();
    __syncthreads();
    if (threadIdx.x == 0) s_tk = atomicAdd(ctr, 1u);
    __syncthreads();
    unsigned int target = (s_tk / GRID + 1u) * GRID;
    if (threadIdx.x == 0) {
        volatile unsigned int* vc = (volatile unsigned int*)ctr;
        while (*vc < target) __nanosleep(32);
    }
    __syncthreads();
    __threadfence();
}

template <bool LCG>
__device__ __forceinline__ float row_dot(const float4* __restrict__ xr4,
                                         const float4* __restrict__ vsm,
                                         int lane) {
    float a0 = 0.0f, a1 = 0.0f;
#pragma unroll
    for (int j = 0; j < 8; j += 2) {
        float4 u0 = LCG ? __ldcg(&xr4[lane + 32 * j])
                        : __ldcs(&xr4[lane + 32 * j]);
        float4 u1 = LCG ? __ldcg(&xr4[lane + 32 * (j + 1)])
                        : __ldcs(&xr4[lane + 32 * (j + 1)]);
        float4 v0 = vsm[lane + 32 * j];
        float4 v1 = vsm[lane + 32 * (j + 1)];
        a0 += u0.x * v0.x + u0.y * v0.y + u0.z * v0.z + u0.w * v0.w;
        a1 += u1.x * v1.x + u1.y * v1.y + u1.z * v1.z + u1.w * v1.w;
    }
    return a0 + a1;
}

// Block-wide softmax over g_scores[sb,:] -> out[sb,:]. noinline protects the
// phase-3 hot-loop register budget.
__device__ __noinline__ void block_softmax(int sb, float* __restrict__ out,
                                           float* red, float* bcast) {
    int tid = threadIdx.x;
    int warp = tid >> 5, lane = tid & 31;

    float s[8];
#pragma unroll
    for (int i = 0; i < 8; i++)
        s[i] = __ldcg(&g_scores[sb * NN + tid + i * 512]);

    float m = s[0];
#pragma unroll
    for (int i = 1; i < 8; i++) m = fmaxf(m, s[i]);
#pragma unroll
    for (int off = 16; off > 0; off >>= 1)
        m = fmaxf(m, __shfl_down_sync(0xFFFFFFFFu, m, off));
    if (lane == 0) red[warp] = m;
    __syncthreads();
    if (warp == 0) {
        float v = (lane < 16) ? red[lane] : -1e30f;
#pragma unroll
        for (int off = 16; off > 0; off >>= 1)
            v = fmaxf(v, __shfl_down_sync(0xFFFFFFFFu, v, off));
        if (lane == 0) *bcast = v;
    }
    __syncthreads();
    float M = *bcast;

    float e[8];
    float local = 0.0f;
#pragma unroll
    for (int i = 0; i < 8; i++) {
        e[i] = expf(s[i] - M);
        local += e[i];
    }
    local = warp_sum(local);
    if (lane == 0) red[warp] = local;
    __syncthreads();
    if (warp == 0) {
        float v = (lane < 16) ? red[lane] : 0.0f;
        v = warp_sum(v);
        if (lane == 0) *bcast = v;
    }
    __syncthreads();
    float inv = 1.0f / *bcast;

#pragma unroll
    for (int i = 0; i < 8; i++)
        out[sb * NN + tid + i * 512] = e[i] * inv;
    __syncthreads();  // protect red/bcast reuse by the caller loop
}

__global__ void __launch_bounds__(512, 2)
k_fused(const float* __restrict__ x, const float* __restrict__ Wq,
        const float* __restrict__ bq, const float* __restrict__ Wk,
        float* __restrict__ out) {
    __shared__ float4 buf4[BB * DIM / 4];  // 32 KB: xs (ph1) / vs (ph3)
    __shared__ float qs[BB][16];           // ph2
    __shared__ float red[16];
    __shared__ float bcast;
    __shared__ unsigned long long s_r0;
    __shared__ int s_sb;

    int tid = threadIdx.x;
    int bx = blockIdx.x;
    int warp = tid >> 5, lane = tid & 31;
    const char* xb = (const char*)x;

    // Epoch/parity: g_b1 == epoch*GRID + (arrivals of this instance so far,
    // < GRID since this block hasn't arrived) -> floor division is exact.
    unsigned int epoch = (*(volatile unsigned int*)&g_b1) / GRID;
    int par = (int)(epoch & 1u);
    unsigned long long tick_base = (unsigned long long)epoch * EPOCH_TICKETS;
    float* gv = g_v2[par];

    // ========= Phase 1 =====================================================
    if (bx < 64) {
        // q0: stage x[b,0,:] (2048 float4, 4/thread), one full e-row per warp.
#pragma unroll
        for (int j = 0; j < 4; j++) {
            int idx = tid + 512 * j;
            int b = idx >> 8, d4 = idx & 255;
            buf4[idx] = ((const float4*)x)[(size_t)b * (NN * DIM / 4) + d4];
        }
        __syncthreads();

        int e = bx * 16 + warp;  // 0..1023
        const float4* wrow4 = (const float4*)Wq + (size_t)e * 256;
        float acc[BB];
#pragma unroll
        for (int b = 0; b < BB; b++) acc[b] = 0.0f;
#pragma unroll
        for (int j = 0; j < 8; j++) {
            int i = lane + 32 * j;
            float4 w4 = wrow4[i];
#pragma unroll
            for (int b = 0; b < BB; b++) {
                float4 x4 = buf4[b * 256 + i];
                acc[b] += w4.x * x4.x + w4.y * x4.y + w4.z * x4.z + w4.w * x4.w;
            }
        }
#pragma unroll
        for (int b = 0; b < BB; b++) acc[b] = warp_sum(acc[b]);
        if (lane == 0) {
            float bias = bq[e];
#pragma unroll
            for (int b = 0; b < BB; b++) g_q0[b * DIM + e] = acc[b] + bias;
        }
    } else if (bx < 128) {
        // Prefetch Wk (4 MB, 1024 rows) into L2 so phase 2 hits L2.
        int pb = bx - 64;                   // 0..63
        int wrow = pb * 16 + warp;          // one 4 KB row per warp
        const char* wkb = (const char*)Wk;
        size_t off = ((size_t)wrow << 12) + ((size_t)lane << 7);
        asm volatile("prefetch.global.L2 [%0];" :: "l"(wkb + off));
    } else {
        // Zero next-parity g_v (for the NEXT replay) + prefetch x rows.
        int gt = (bx - 128) * 512 + tid;
        if (gt < BB * DIM) g_v2[1 - par][gt] = 0.0f;

        int pb = bx - 128;                  // 0..167
        int r0 = pb * 48 + warp * 3;        // 8064 rows = 31.5 MB
#pragma unroll
        for (int k = 0; k < 3; k++) {
            size_t off = ((size_t)(r0 + k) << 12) + ((size_t)lane << 7);
            asm volatile("prefetch.global.L2 [%0];" :: "l"(xb + off));
        }
    }

    grid_barrier(&g_b1);

    // ========= Phase 2: v[b,d] += q0[b,e-chunk]·Wk[e-chunk,d] =============
    if (bx < 128) {
        int e0 = (bx >> 1) * 16;
        int d = (bx & 1) * 512 + tid;
        if (tid < BB * 16) {
            int b = tid >> 4, j = tid & 15;
            qs[b][j] = __ldcg(&g_q0[b * DIM + e0 + j]);
        }
        __syncthreads();

        float vacc[BB];
#pragma unroll
        for (int b = 0; b < BB; b++) vacc[b] = 0.0f;
#pragma unroll
        for (int j = 0; j < 16; j++) {
            float w = __ldcg(&Wk[(size_t)(e0 + j) * DIM + d]);  // L2 hit
#pragma unroll
            for (int b = 0; b < BB; b++) vacc[b] += qs[b][j] * w;
        }
#pragma unroll
        for (int b = 0; b < BB; b++) atomicAdd(&gv[b * DIM + d], vacc[b]);
    }

    grid_barrier(&g_b2);

    // ========= Phase 3: scores + inline per-batch softmax =================
#pragma unroll
    for (int j = 0; j < 4; j++) {
        int idx = tid + 512 * j;
        buf4[idx] = __ldcg((const float4*)gv + idx);
    }
    __syncthreads();

    for (;;) {
        if (tid == 0) s_r0 = atomicAdd(&g_row, (unsigned long long)CHUNK);
        __syncthreads();
        unsigned long long rabs = s_r0;
        long long rrel = (long long)(rabs - tick_base);
        if (rrel >= TOTAL_ROWS) break;
        int r0 = (int)rrel;
        int cb = r0 >> 12;                     // chunk batch (CHUNK divides NN)
        bool inL2 = (r0 < PF_ROWS);
#pragma unroll
        for (int k = 0; k < 2; k++) {
            int r = r0 + k * 16 + warp;
            const float4* xr4 = (const float4*)x + (size_t)r * 256;
            const float4* vsm = buf4 + cb * 256;
            float acc = inL2 ? row_dot<true>(xr4, vsm, lane)
                             : row_dot<false>(xr4, vsm, lane);
            acc = warp_sum(acc);
            if (lane == 0) g_scores[r] = acc;
        }

        // Release this chunk; the block completing a batch runs its softmax.
        __threadfence();
        __syncthreads();
        if (tid == 0) {
            unsigned int old = atomicAdd(&g_done[cb], (unsigned)CHUNK);
            s_sb = (((old + CHUNK) & (NN - 1)) == 0) ? cb : -1;
        }
        __syncthreads();
        if (s_sb >= 0) {
            __threadfence();
            block_softmax(s_sb, out, red, &bcast);
        }
    }
}

extern "C" void kernel_launch(void* const* d_in, const int* in_sizes, int n_in,
                              void* d_out, int out_size) {
    const float* x  = (const float*)d_in[0];
    const float* Wq = (const float*)d_in[1];
    const float* bq = (const float*)d_in[2];
    const float* Wk = (const float*)d_in[3];
    // bk (d_in[4]) is mathematically dead: it shifts every score in a row by
    // the same constant, which cancels in softmax.
    float* out = (float*)d_out;

    k_fused<<<GRID, 512>>>(x, Wq, bq, Wk, out);
}

// round 15
// speedup vs baseline: 1.0616x; 1.0616x over previous
#include <cuda_runtime.h>
#include <math.h>

#define BB 8
#define NN 4096
#define DIM 1024
#define GRID 296            // 148 SMs x 2 CTAs, all resident
#define TOTAL_ROWS (BB * NN)
#define CHUNK 32            // rows per dynamic grab
#define PF_ROWS 8064        // rows L2-prefetched during prepass (31.5 MB) [R11 proven]

// Scratch (no allocation allowed). Zero at load; re-zeroed at end of each run.
__device__ float g_q0[BB * DIM];
__device__ float g_v[BB * DIM];
__device__ float g_scores[BB * NN];
__device__ unsigned int g_b1, g_b2, g_b3;  // monotonic barrier counters
__device__ unsigned int g_row;             // phase-3 ticket (reset at end)

__device__ __forceinline__ float warp_sum(float v) {
#pragma unroll
    for (int off = 16; off > 0; off >>= 1)
        v += __shfl_down_sync(0xFFFFFFFFu, v, off);
    return v;
}

// Monotonic grid barrier: safe across graph replays (counter never resets).
// Arrival uses one atomicAdd; the wait polls with a plain volatile LOAD.
__device__ __forceinline__ void grid_barrier(unsigned int* ctr) {
    __shared__ unsigned int s_tk;
    __threadfence();
    __syncthreads();
    if (threadIdx.x == 0) s_tk = atomicAdd(ctr, 1u);
    __syncthreads();
    unsigned int target = (s_tk / GRID + 1u) * GRID;
    if (threadIdx.x == 0) {
        volatile unsigned int* vc = (volatile unsigned int*)ctr;
        while (*vc < target) __nanosleep(32);
    }
    __syncthreads();
    __threadfence();
}

// One row-dot: x[r,:] (1024 f32) . v (in smem). LCG: L2-resident path.
template <bool LCG>
__device__ __forceinline__ float row_dot(const float4* __restrict__ xr4,
                                         const float4* __restrict__ vsm,
                                         int lane) {
    float a0 = 0.0f, a1 = 0.0f;
#pragma unroll
    for (int j = 0; j < 8; j += 2) {
        float4 u0 = LCG ? __ldcg(&xr4[lane + 32 * j])
                        : __ldcs(&xr4[lane + 32 * j]);
        float4 u1 = LCG ? __ldcg(&xr4[lane + 32 * (j + 1)])
                        : __ldcs(&xr4[lane + 32 * (j + 1)]);
        float4 v0 = vsm[lane + 32 * j];
        float4 v1 = vsm[lane + 32 * (j + 1)];
        a0 += u0.x * v0.x + u0.y * v0.y + u0.z * v0.z + u0.w * v0.w;
        a1 += u1.x * v1.x + u1.y * v1.y + u1.z * v1.z + u1.w * v1.w;
    }
    return a0 + a1;
}

__global__ void __launch_bounds__(512, 2)
k_fused(const float* __restrict__ x, const float* __restrict__ Wq,
        const float* __restrict__ bq, const float* __restrict__ Wk,
        float* __restrict__ out) {
    __shared__ float4 buf4[BB * DIM / 4];  // 32 KB: xs (ph1) / vs (ph3)
    __shared__ float qs[BB][16];           // ph2
    __shared__ float red[16];
    __shared__ float bcast;
    __shared__ unsigned int s_r0;

    int tid = threadIdx.x;
    int bx = blockIdx.x;
    int warp = tid >> 5, lane = tid & 31;
    const char* xb = (const char*)x;

    // ========= Phase 1 (blocks 0..127): q0 = Wq@x0 + bq  (atomic halves) ==
    // Blocks 128..295: fire-and-forget L2 prefetch of x rows 0..PF_ROWS-1,
    // plus the whole of Wk (4 MB) so phase 2 hits L2.
    if (bx < 128) {
        // stage x[b,0,:]: 2048 float4 over 512 threads (MLP 4)
#pragma unroll
        for (int j = 0; j < 4; j++) {
            int idx = tid + 512 * j;
            int b = idx >> 8, d4 = idx & 255;
            buf4[idx] = ((const float4*)x)[(size_t)b * (NN * DIM / 4) + d4];
        }
        __syncthreads();

        int gw = bx * 16 + warp;      // 0..2047
        int e = gw >> 1;
        int h = gw & 1;
        int base = h * 128;           // float4 offset within row
        const float4* wrow4 = (const float4*)Wq + (size_t)e * 256 + base;

        float acc[BB];
#pragma unroll
        for (int b = 0; b < BB; b++) acc[b] = 0.0f;
#pragma unroll
        for (int j = 0; j < 4; j++) {
            int i = lane + 32 * j;
            float4 w4 = wrow4[i];
#pragma unroll
            for (int b = 0; b < BB; b++) {
                float4 x4 = buf4[b * 256 + base + i];
                acc[b] += w4.x * x4.x + w4.y * x4.y + w4.z * x4.z + w4.w * x4.w;
            }
        }
#pragma unroll
        for (int b = 0; b < BB; b++) acc[b] = warp_sum(acc[b]);
        if (lane == 0) {
            float bias = (h == 0) ? bq[e] : 0.0f;
#pragma unroll
            for (int b = 0; b < BB; b++)
                atomicAdd(&g_q0[b * DIM + e], acc[b] + bias);
        }
    } else {
        // x: 168 blocks x 48 rows = 8064 rows = 31.5 MB into L2.
        int pb = bx - 128;                 // 0..167
        int r0 = pb * 48 + warp * 3;       // each warp: 3 rows
#pragma unroll
        for (int k = 0; k < 3; k++) {
            size_t off = ((size_t)(r0 + k) << 12) + ((size_t)lane << 7);
            asm volatile("prefetch.global.L2 [%0];" :: "l"(xb + off));
        }
        // Wk: first 1024 prefetch-warps take one 4 KB row each (4 MB).
        int gw = pb * 16 + warp;           // 0..2687
        if (gw < DIM) {
            const char* wkb = (const char*)Wk;
            size_t off = ((size_t)gw << 12) + ((size_t)lane << 7);
            asm volatile("prefetch.global.L2 [%0];" :: "l"(wkb + off));
        }
    }

    grid_barrier(&g_b1);

    // ========= Phase 2: v[b,d] += q0[b,e-chunk]·Wk[e-chunk,d] =============
    // 128 blocks: 64 e-chunks (16 e) x 2 d-halves (512 d). g_v pre-zeroed.
    if (bx < 128) {
        int e0 = (bx >> 1) * 16;
        int d = (bx & 1) * 512 + tid;
        if (tid < BB * 16) {
            int b = tid >> 4, j = tid & 15;
            qs[b][j] = __ldcg(&g_q0[b * DIM + e0 + j]);
        }
        __syncthreads();

        float vacc[BB];
#pragma unroll
        for (int b = 0; b < BB; b++) vacc[b] = 0.0f;
#pragma unroll
        for (int j = 0; j < 16; j++) {
            float w = __ldcg(&Wk[(size_t)(e0 + j) * DIM + d]);  // L2 hit (prefetched)
#pragma unroll
            for (int b = 0; b < BB; b++) vacc[b] += qs[b][j] * w;
        }
#pragma unroll
        for (int b = 0; b < BB; b++) atomicAdd(&g_v[b * DIM + d], vacc[b]);
    }

    grid_barrier(&g_b2);

    // ========= Phase 3: scores[r] = x[r,:]·v[b(r),:]  (dynamic chunks) ====
#pragma unroll
    for (int j = 0; j < 4; j++) {
        int idx = tid + 512 * j;
        buf4[idx] = __ldcg((const float4*)g_v + idx);
    }
    __syncthreads();

    for (;;) {
        if (tid == 0) s_r0 = atomicAdd(&g_row, (unsigned)CHUNK);
        __syncthreads();
        unsigned int r0 = s_r0;
        if (r0 >= (unsigned)TOTAL_ROWS) break;
        bool inL2 = (r0 < (unsigned)PF_ROWS);  // PF_ROWS is CHUNK-aligned
#pragma unroll
        for (int k = 0; k < 2; k++) {
            int r = (int)r0 + k * 16 + warp;
            int b = r >> 12;
            const float4* xr4 = (const float4*)x + (size_t)r * 256;
            const float4* vsm = buf4 + b * 256;
            float acc = inL2 ? row_dot<true>(xr4, vsm, lane)
                             : row_dot<false>(xr4, vsm, lane);
            acc = warp_sum(acc);
            if (lane == 0) g_scores[r] = acc;
        }
        __syncthreads();
    }

    grid_barrier(&g_b3);

    // ========= End-of-run housekeeping (for next replay) ==================
    if (bx >= 8 && bx < 24) {
        g_v[(bx - 8) * 512 + tid] = 0.0f;
    } else if (bx >= 24 && bx < 40) {
        g_q0[(bx - 24) * 512 + tid] = 0.0f;
    } else if (bx == 40 && tid == 0) {
        g_row = 0u;
    }

    // ========= Phase 4: softmax, blocks 0..7 ==============================
    if (bx >= 8) return;
    int sb = bx;

    float s[8];
#pragma unroll
    for (int i = 0; i < 8; i++)
        s[i] = __ldcg(&g_scores[sb * NN + tid + i * 512]);

    float m = s[0];
#pragma unroll
    for (int i = 1; i < 8; i++) m = fmaxf(m, s[i]);
#pragma unroll
    for (int off = 16; off > 0; off >>= 1)
        m = fmaxf(m, __shfl_down_sync(0xFFFFFFFFu, m, off));
    if (lane == 0) red[warp] = m;
    __syncthreads();
    if (warp == 0) {
        float v = (lane < 16) ? red[lane] : -1e30f;
#pragma unroll
        for (int off = 16; off > 0; off >>= 1)
            v = fmaxf(v, __shfl_down_sync(0xFFFFFFFFu, v, off));
        if (lane == 0) bcast = v;
    }
    __syncthreads();
    float M = bcast;

    float e[8];
    float local = 0.0f;
#pragma unroll
    for (int i = 0; i < 8; i++) {
        e[i] = expf(s[i] - M);
        local += e[i];
    }
    local = warp_sum(local);
    if (lane == 0) red[warp] = local;
    __syncthreads();
    if (warp == 0) {
        float v = (lane < 16) ? red[lane] : 0.0f;
        v = warp_sum(v);
        if (lane == 0) bcast = v;
    }
    __syncthreads();
    float inv = 1.0f / bcast;

#pragma unroll
    for (int i = 0; i < 8; i++)
        out[sb * NN + tid + i * 512] = e[i] * inv;
}

extern "C" void kernel_launch(void* const* d_in, const int* in_sizes, int n_in,
                              void* d_out, int out_size) {
    const float* x  = (const float*)d_in[0];
    const float* Wq = (const float*)d_in[1];
    const float* bq = (const float*)d_in[2];
    const float* Wk = (const float*)d_in[3];
    // bk (d_in[4]) is mathematically dead: it shifts every score in a row by
    // the same constant, which cancels in softmax.
    float* out = (float*)d_out;

    k_fused<<<GRID, 512>>>(x, Wq, bq, Wk, out);
}